// round 14
// baseline (speedup 1.0000x reference)
#include <cuda_runtime.h>
#include <cuda_bf16.h>
#include <cstdint>

// ============================================================================
// Fused 2-layer SimpleRNN, round 10 (resubmit after infra failure in R13).
//  (a) recurrence reordered so both tanh phases overlap independent MMA
//      blocks:  tanh(h1) || h2@Wh2,  tanh(h2) || h1@Wh1 (+E' ldsm).
//  (b) CTA = 1 warp (16 batch rows), grid = 1024 -> all 148 SMs used,
//      max 7 warps/SM (was 8 on 128 SMs). Weights pre-converted to bf16
//      tiles by a prep kernel; per-CTA init is plain uint4 copies.
//  (c) fp32 tanh (R9's bf16x2 tanh was slower and less accurate).
// ============================================================================

#define VOCAB   10000
#define B_TOT   16384
#define T_SEQ   80
#define E_DIM   100
#define U_DIM   64
#define NTHR    32          // one warp per CTA
#define NCTA    (B_TOT / 16)

#define HSTRB   144         // W tile row stride bytes (72 bf16)
#define TILE_B  (U_DIM * HSTRB)   // 9216 B per weight tile
#define STGSTR  144
#define STG_B   (16 * STGSTR)     // 2304 B

// Projected embedding table: E'[v][u] = emb[v]@Wx1[:,u] + b1[u]  (bf16)
__device__ __nv_bfloat16 g_Etab[VOCAB * U_DIM];
// Pre-transposed bf16 weight tiles [n][k], stride 72, k>=64 zero:
// [0]=Wh1, [1]=Wx2, [2]=Wh2
__device__ __align__(16) __nv_bfloat16 g_wt[3][U_DIM * 72];

// ---------------------------------------------------------------------------
__device__ __forceinline__ uint32_t smem_u32(const void* p) {
    uint32_t a;
    asm("{ .reg .u64 t; cvta.to.shared.u64 t, %1; cvt.u32.u64 %0, t; }"
        : "=r"(a) : "l"(p));
    return a;
}
__device__ __forceinline__ float tanh_fast(float x) {
    float y; asm("tanh.approx.f32 %0, %1;" : "=f"(y) : "f"(x)); return y;
}
__device__ __forceinline__ uint32_t pack_bf16x2(float lo, float hi) {
    uint32_t r;
    asm("cvt.rn.bf16x2.f32 %0, %1, %2;" : "=r"(r) : "f"(hi), "f"(lo));
    return r;
}
__device__ __forceinline__ float bf16_lo(uint32_t p) { return __uint_as_float(p << 16); }
__device__ __forceinline__ float bf16_hi(uint32_t p) { return __uint_as_float(p & 0xffff0000u); }

__device__ __forceinline__ void ldsm4(uint32_t a[4], uint32_t addr) {
    asm volatile("ldmatrix.sync.aligned.m8n8.x4.shared.b16 {%0,%1,%2,%3}, [%4];"
                 : "=r"(a[0]), "=r"(a[1]), "=r"(a[2]), "=r"(a[3]) : "r"(addr));
}
__device__ __forceinline__ void mma16816(float c[4], const uint32_t a[4],
                                         uint32_t b0, uint32_t b1) {
    asm volatile("mma.sync.aligned.m16n8k16.row.col.f32.bf16.bf16.f32 "
                 "{%0,%1,%2,%3}, {%4,%5,%6,%7}, {%8,%9}, {%0,%1,%2,%3};"
                 : "+f"(c[0]), "+f"(c[1]), "+f"(c[2]), "+f"(c[3])
                 : "r"(a[0]), "r"(a[1]), "r"(a[2]), "r"(a[3]),
                   "r"(b0), "r"(b1));
}

// ---------------------------------------------------------------------------
// Kernel 1: E'[v] = emb[v] @ Wx1 + b1.  16 vocab rows/block, Wx1 in SMEM.
// ---------------------------------------------------------------------------
#define XP_ROWS 16
__global__ void __launch_bounds__(256)
xproj_kernel(const float* __restrict__ emb,
             const float* __restrict__ Wx1,
             const float* __restrict__ b1)
{
    __shared__ float wxs[E_DIM * U_DIM];
    __shared__ float er[XP_ROWS][E_DIM];
    const int tid = threadIdx.x;
    const int v0  = blockIdx.x * XP_ROWS;

    for (int i = tid; i < E_DIM * U_DIM; i += 256) wxs[i] = __ldg(Wx1 + i);
    for (int i = tid; i < XP_ROWS * E_DIM; i += 256) {
        int v = i / E_DIM, k = i - v * E_DIM;
        er[v][k] = (v0 + v < VOCAB) ? emb[(size_t)(v0 + v) * E_DIM + k] : 0.0f;
    }
    __syncthreads();

    const int u  = tid & 63;
    const int ry = tid >> 6;
    const float bias = __ldg(b1 + u);
#pragma unroll
    for (int rr = 0; rr < 4; rr++) {
        const int r = ry * 4 + rr;
        const int v = v0 + r;
        if (v >= VOCAB) break;
        float s = bias;
        const float4* er4 = (const float4*)er[r];
#pragma unroll 5
        for (int kc = 0; kc < E_DIM / 4; kc++) {
            float4 e = er4[kc];
            s = fmaf(e.x, wxs[(4 * kc + 0) * U_DIM + u], s);
            s = fmaf(e.y, wxs[(4 * kc + 1) * U_DIM + u], s);
            s = fmaf(e.z, wxs[(4 * kc + 2) * U_DIM + u], s);
            s = fmaf(e.w, wxs[(4 * kc + 3) * U_DIM + u], s);
        }
        g_Etab[v * U_DIM + u] = __float2bfloat16(s);
    }
}

// ---------------------------------------------------------------------------
// Kernel 1b: weight tiles -> bf16 [n][k] stride 72 (k>=64 zero)
// ---------------------------------------------------------------------------
__global__ void wprep_kernel(const float* __restrict__ Wh1,
                             const float* __restrict__ Wx2,
                             const float* __restrict__ Wh2)
{
    const float* src[3] = { Wh1, Wx2, Wh2 };
    int tile = blockIdx.x;
    const float* w = src[tile];
    for (int i = threadIdx.x; i < U_DIM * 72; i += blockDim.x) {
        int n = i / 72, k = i - n * 72;
        g_wt[tile][i] = (k < U_DIM) ? __float2bfloat16(w[k * U_DIM + n])
                                    : __float2bfloat16(0.0f);
    }
}

// ---------------------------------------------------------------------------
// Kernel 2: recurrent loop. CTA = 1 warp = 16 batch rows.
// ---------------------------------------------------------------------------
__global__ void __launch_bounds__(NTHR, 1)
rnn_loop_kernel(const int* __restrict__ tokens,
                const float* __restrict__ b2,
                const float* __restrict__ Wd, const float* __restrict__ bd,
                float* __restrict__ out)
{
    __shared__ __align__(16) unsigned char sm[TILE_B + STG_B + 16];
    const uint32_t smb = smem_u32(sm);

    const int lane = threadIdx.x;
    const int growbase = blockIdx.x * 16;

    // ---- ldmatrix lane addressing ----------------------------------------
    const uint32_t aRow = (uint32_t)(lane & 15);
    const uint32_t aK16 = (uint32_t)(lane >> 4) * 16;
    const uint32_t bRow = (uint32_t)((lane & 7) + ((lane >> 4) << 3));
    const uint32_t bK16 = (uint32_t)((lane >> 3) & 1) * 16;

    const uint32_t wB_lane = smb + bRow * HSTRB + bK16;   // tile at SMEM base
    const int cr = lane >> 2;
    const int cq = (lane & 3) * 2;

    // ---- load layer-2 weights into registers via SMEM bounce --------------
    uint32_t wx2r[4][4][4], wh2r[4][4][4];
    {
        const uint4* src = (const uint4*)g_wt[1];          // Wx2 tile
        uint4* dst = (uint4*)sm;
#pragma unroll
        for (int i = 0; i < TILE_B / 512; i++) dst[lane + 32 * i] = __ldg(src + lane + 32 * i);
        __syncwarp();
#pragma unroll
        for (int kt = 0; kt < 4; kt++)
#pragma unroll
            for (int np = 0; np < 4; np++)
                ldsm4(wx2r[kt][np], wB_lane + np * 16 * HSTRB + kt * 32);
        __syncwarp();
        src = (const uint4*)g_wt[2];                        // Wh2 tile
#pragma unroll
        for (int i = 0; i < TILE_B / 512; i++) dst[lane + 32 * i] = __ldg(src + lane + 32 * i);
        __syncwarp();
#pragma unroll
        for (int kt = 0; kt < 4; kt++)
#pragma unroll
            for (int np = 0; np < 4; np++)
                ldsm4(wh2r[kt][np], wB_lane + np * 16 * HSTRB + kt * 32);
        __syncwarp();
        src = (const uint4*)g_wt[0];                        // Wh1 tile (stays)
#pragma unroll
        for (int i = 0; i < TILE_B / 512; i++) dst[lane + 32 * i] = __ldg(src + lane + 32 * i);
        __syncwarp();
    }

    // ---- E' staging addresses --------------------------------------------
    const uint32_t stgA_lane = smb + TILE_B + aRow * STGSTR + aK16;   // ldsm read
    const int ldg_row   = lane >> 3;
    const int ldg_chunk = lane & 7;
    unsigned char* stg_ptr = sm + TILE_B + ldg_chunk * 16;

    // ---- per-lane b2 -----------------------------------------------------
    float b2x[8], b2y[8];
#pragma unroll
    for (int nt = 0; nt < 8; nt++) {
        b2x[nt] = __ldg(b2 + nt * 8 + cq);
        b2y[nt] = __ldg(b2 + nt * 8 + cq + 1);
    }

    // ---- state fragments --------------------------------------------------
    uint32_t h1f[4][4], h2f[4][4];
#pragma unroll
    for (int kt = 0; kt < 4; kt++)
#pragma unroll
        for (int j = 0; j < 4; j++) { h1f[kt][j] = 0u; h2f[kt][j] = 0u; }

    // ---- prefetch machinery ----------------------------------------------
    const uint4* Et4 = (const uint4*)g_Etab;
    uint4 pv[4];
    int tokreg = 0;

    auto prefetch_load = [&](int t) {
        int r = 0;
        if (lane < 16) r = __ldg(tokens + (size_t)(growbase + lane) * T_SEQ + t);
        tokreg = r;
#pragma unroll
        for (int i = 0; i < 4; i++) {
            int row = 4 * i + ldg_row;
            int tok = __shfl_sync(0xffffffffu, tokreg, row);
            pv[i] = __ldg(Et4 + (size_t)tok * 8 + ldg_chunk);
        }
    };
    auto prefetch_store = [&]() {
#pragma unroll
        for (int i = 0; i < 4; i++) {
            int row = 4 * i + ldg_row;
            *(uint4*)(stg_ptr + row * STGSTR) = pv[i];
        }
    };

    // ---- prologue: acc = E'(0); stage E'(1); pv = E'(2) -------------------
    float acc[8][4];
    prefetch_load(0);
    prefetch_store();
    __syncwarp();
    {
#pragma unroll
        for (int kc = 0; kc < 4; kc++) {
            uint32_t e[4]; ldsm4(e, stgA_lane + kc * 32);
            acc[2 * kc][0]     = bf16_lo(e[0]); acc[2 * kc][1]     = bf16_hi(e[0]);
            acc[2 * kc][2]     = bf16_lo(e[1]); acc[2 * kc][3]     = bf16_hi(e[1]);
            acc[2 * kc + 1][0] = bf16_lo(e[2]); acc[2 * kc + 1][1] = bf16_hi(e[2]);
            acc[2 * kc + 1][2] = bf16_lo(e[3]); acc[2 * kc + 1][3] = bf16_hi(e[3]);
        }
    }
    __syncwarp();
    prefetch_load(1);
    prefetch_store();
    __syncwarp();
    prefetch_load(2);

    // ---- main loop: t = 0..78 (full pipeline) -----------------------------
    // invariant entering iter t: acc = pre-activation of layer1 step t;
    // staging holds E'(t+1); pv holds E'(t+2); h2f = h2(t-1).
    for (int t = 0; t < T_SEQ - 1; ++t) {
        // == phase A: h1 = tanh(acc)  ||  accB = b2 + h2@Wh2 (independent) ==
#pragma unroll
        for (int kt = 0; kt < 4; kt++) {
            h1f[kt][0] = pack_bf16x2(tanh_fast(acc[2 * kt][0]),     tanh_fast(acc[2 * kt][1]));
            h1f[kt][1] = pack_bf16x2(tanh_fast(acc[2 * kt][2]),     tanh_fast(acc[2 * kt][3]));
            h1f[kt][2] = pack_bf16x2(tanh_fast(acc[2 * kt + 1][0]), tanh_fast(acc[2 * kt + 1][1]));
            h1f[kt][3] = pack_bf16x2(tanh_fast(acc[2 * kt + 1][2]), tanh_fast(acc[2 * kt + 1][3]));
        }
#pragma unroll
        for (int nt = 0; nt < 8; nt++) {
            acc[nt][0] = b2x[nt]; acc[nt][1] = b2y[nt];
            acc[nt][2] = b2x[nt]; acc[nt][3] = b2y[nt];
        }
#pragma unroll
        for (int kt = 0; kt < 4; kt++)
#pragma unroll
            for (int np = 0; np < 4; np++) {
                mma16816(acc[2 * np],     h2f[kt], wh2r[kt][np][0], wh2r[kt][np][1]);
                mma16816(acc[2 * np + 1], h2f[kt], wh2r[kt][np][2], wh2r[kt][np][3]);
            }

        // == phase B: acc += h1@Wx2 ==
#pragma unroll
        for (int kt = 0; kt < 4; kt++)
#pragma unroll
            for (int np = 0; np < 4; np++) {
                mma16816(acc[2 * np],     h1f[kt], wx2r[kt][np][0], wx2r[kt][np][1]);
                mma16816(acc[2 * np + 1], h1f[kt], wx2r[kt][np][2], wx2r[kt][np][3]);
            }

        // == phase C: h2 = tanh(acc)  ||  acc = E'(t+1) + h1@Wh1 ==
        uint32_t e[4][4];
#pragma unroll
        for (int kc = 0; kc < 4; kc++) ldsm4(e[kc], stgA_lane + kc * 32);
#pragma unroll
        for (int kt = 0; kt < 4; kt++) {
            h2f[kt][0] = pack_bf16x2(tanh_fast(acc[2 * kt][0]),     tanh_fast(acc[2 * kt][1]));
            h2f[kt][1] = pack_bf16x2(tanh_fast(acc[2 * kt][2]),     tanh_fast(acc[2 * kt][3]));
            h2f[kt][2] = pack_bf16x2(tanh_fast(acc[2 * kt + 1][0]), tanh_fast(acc[2 * kt + 1][1]));
            h2f[kt][3] = pack_bf16x2(tanh_fast(acc[2 * kt + 1][2]), tanh_fast(acc[2 * kt + 1][3]));
        }
#pragma unroll
        for (int kc = 0; kc < 4; kc++) {
            acc[2 * kc][0]     = bf16_lo(e[kc][0]); acc[2 * kc][1]     = bf16_hi(e[kc][0]);
            acc[2 * kc][2]     = bf16_lo(e[kc][1]); acc[2 * kc][3]     = bf16_hi(e[kc][1]);
            acc[2 * kc + 1][0] = bf16_lo(e[kc][2]); acc[2 * kc + 1][1] = bf16_hi(e[kc][2]);
            acc[2 * kc + 1][2] = bf16_lo(e[kc][3]); acc[2 * kc + 1][3] = bf16_hi(e[kc][3]);
        }
#pragma unroll
        for (int kt = 0; kt < 4; kt++)
#pragma unroll
            for (int np = 0; np < 4; np++) {
                uint32_t b[4]; ldsm4(b, wB_lane + np * 16 * HSTRB + kt * 32);
                mma16816(acc[2 * np],     h1f[kt], b[0], b[1]);
                mma16816(acc[2 * np + 1], h1f[kt], b[2], b[3]);
            }

        // staging rotate: ldsm(E'(t+1)) done above -> overwrite with E'(t+2)
        __syncwarp();
        if (t <= T_SEQ - 3) prefetch_store();
        if (t <= T_SEQ - 4) prefetch_load(t + 3);
        __syncwarp();
    }

    // ---- final step t = 79 (no next acc) ----------------------------------
#pragma unroll
    for (int kt = 0; kt < 4; kt++) {
        h1f[kt][0] = pack_bf16x2(tanh_fast(acc[2 * kt][0]),     tanh_fast(acc[2 * kt][1]));
        h1f[kt][1] = pack_bf16x2(tanh_fast(acc[2 * kt][2]),     tanh_fast(acc[2 * kt][3]));
        h1f[kt][2] = pack_bf16x2(tanh_fast(acc[2 * kt + 1][0]), tanh_fast(acc[2 * kt + 1][1]));
        h1f[kt][3] = pack_bf16x2(tanh_fast(acc[2 * kt + 1][2]), tanh_fast(acc[2 * kt + 1][3]));
    }
#pragma unroll
    for (int nt = 0; nt < 8; nt++) {
        acc[nt][0] = b2x[nt]; acc[nt][1] = b2y[nt];
        acc[nt][2] = b2x[nt]; acc[nt][3] = b2y[nt];
    }
#pragma unroll
    for (int kt = 0; kt < 4; kt++)
#pragma unroll
        for (int np = 0; np < 4; np++) {
            mma16816(acc[2 * np],     h2f[kt], wh2r[kt][np][0], wh2r[kt][np][1]);
            mma16816(acc[2 * np + 1], h2f[kt], wh2r[kt][np][2], wh2r[kt][np][3]);
            mma16816(acc[2 * np],     h1f[kt], wx2r[kt][np][0], wx2r[kt][np][1]);
            mma16816(acc[2 * np + 1], h1f[kt], wx2r[kt][np][2], wx2r[kt][np][3]);
        }
#pragma unroll
    for (int kt = 0; kt < 4; kt++) {
        h2f[kt][0] = pack_bf16x2(tanh_fast(acc[2 * kt][0]),     tanh_fast(acc[2 * kt][1]));
        h2f[kt][1] = pack_bf16x2(tanh_fast(acc[2 * kt][2]),     tanh_fast(acc[2 * kt][3]));
        h2f[kt][2] = pack_bf16x2(tanh_fast(acc[2 * kt + 1][0]), tanh_fast(acc[2 * kt + 1][1]));
        h2f[kt][3] = pack_bf16x2(tanh_fast(acc[2 * kt + 1][2]), tanh_fast(acc[2 * kt + 1][3]));
    }

    // ---- final dense + sigmoid -------------------------------------------
    // row cr: frags [0] (cols 16kt+cq), [2] (cols 16kt+8+cq); row cr+8: [1],[3]
    {
        float la = 0.0f, lb = 0.0f;
#pragma unroll
        for (int kt = 0; kt < 4; kt++) {
            int c0 = 16 * kt + cq;
            float w0 = __ldg(Wd + c0),     w1 = __ldg(Wd + c0 + 1);
            float w8 = __ldg(Wd + c0 + 8), w9 = __ldg(Wd + c0 + 9);
            la = fmaf(bf16_lo(h2f[kt][0]), w0, la);
            la = fmaf(bf16_hi(h2f[kt][0]), w1, la);
            la = fmaf(bf16_lo(h2f[kt][2]), w8, la);
            la = fmaf(bf16_hi(h2f[kt][2]), w9, la);
            lb = fmaf(bf16_lo(h2f[kt][1]), w0, lb);
            lb = fmaf(bf16_hi(h2f[kt][1]), w1, lb);
            lb = fmaf(bf16_lo(h2f[kt][3]), w8, lb);
            lb = fmaf(bf16_hi(h2f[kt][3]), w9, lb);
        }
        la += __shfl_xor_sync(0xffffffffu, la, 1);
        la += __shfl_xor_sync(0xffffffffu, la, 2);
        lb += __shfl_xor_sync(0xffffffffu, lb, 1);
        lb += __shfl_xor_sync(0xffffffffu, lb, 2);
        if ((lane & 3) == 0) {
            float bdv = __ldg(bd);
            out[growbase + cr]     = 1.0f / (1.0f + __expf(-(la + bdv)));
            out[growbase + cr + 8] = 1.0f / (1.0f + __expf(-(lb + bdv)));
        }
    }
}

// ---------------------------------------------------------------------------
extern "C" void kernel_launch(void* const* d_in, const int* in_sizes, int n_in,
                              void* d_out, int out_size) {
    (void)in_sizes; (void)n_in; (void)out_size;

    xproj_kernel<<<(VOCAB + XP_ROWS - 1) / XP_ROWS, 256>>>(
        (const float*)d_in[1],   // emb
        (const float*)d_in[2],   // Wx1
        (const float*)d_in[4]);  // b1

    wprep_kernel<<<3, 256>>>(
        (const float*)d_in[3],   // Wh1
        (const float*)d_in[5],   // Wx2
        (const float*)d_in[6]);  // Wh2

    rnn_loop_kernel<<<NCTA, NTHR>>>(
        (const int*)d_in[0],     // tokens
        (const float*)d_in[7],   // b2
        (const float*)d_in[8],   // Wd
        (const float*)d_in[9],   // bd
        (float*)d_out);
}